// round 1
// baseline (speedup 1.0000x reference)
#include <cuda_runtime.h>
#include <cstdint>

// ---------------------------------------------------------------------------
// TT embedding lookup, grouped by i1 (the 256KB core1 row gather).
// P=(216,216,216), Q=(2,4,2), R=(128,128), 2 tables, batch 1024.
// out[t, b, (q0*4+q1)*2+q2] = sum_{r0,r1} A[q0,r0] * Bm[r0, q1*128+r1] * C[r1,q2]
// ---------------------------------------------------------------------------

#define NTAB 2
#define BATCH 1024
#define NSAMP (NTAB * BATCH)
#define P0 216
#define P12 46656LL
#define NBUCKET (NTAB * 216)
#define CORE1_ROW 65536   // 128 * 4 * 128 floats
#define CORE02_ROW 256    // 2*128 / 128*2 floats
#define CHUNK 8

__device__ int   g_counts[NBUCKET];
__device__ int   g_offsets[NBUCKET + 1];
__device__ int   g_cursor[NBUCKET];
__device__ int   g_order[NSAMP];
__device__ int   g_i0[NSAMP];
__device__ int   g_i2[NSAMP];
__device__ short g_bk[NSAMP];

// ---------------------------------------------------------------------------
// Phase A: decode indices, bucket-sort by (table, i1). Single CTA.
// Auto-detects int64 vs int32 index payload (JAX may downgrade jnp.int64).
// ---------------------------------------------------------------------------
__global__ void build_buckets(const void* __restrict__ idx_raw) {
    const int tid = threadIdx.x;  // 1024 threads

    for (int i = tid; i < NBUCKET; i += 1024) g_counts[i] = 0;
    __syncthreads();

    const long long* p64 = (const long long*)idx_raw;
    const int*       p32 = (const int*)idx_raw;
    bool is64 = true;
    #pragma unroll
    for (int j = 0; j < 4; j++) {
        long long v = p64[j];
        if (v < 0 || v >= 10000000LL) is64 = false;
    }

    for (int s = tid; s < NSAMP; s += 1024) {
        long long idx = is64 ? p64[s] : (long long)p32[s];
        int i0 = (int)(idx / P12);
        int i1 = (int)((idx / 216) % 216);
        int i2 = (int)(idx % 216);
        int table = s >> 10;
        int b = table * 216 + i1;
        g_i0[s] = i0;
        g_i2[s] = i2;
        g_bk[s] = (short)b;
        atomicAdd(&g_counts[b], 1);
    }
    __syncthreads();

    if (tid == 0) {
        int run = 0;
        for (int i = 0; i < NBUCKET; i++) {
            g_offsets[i] = run;
            run += g_counts[i];
        }
        g_offsets[NBUCKET] = run;
    }
    __syncthreads();

    for (int i = tid; i < NBUCKET; i += 1024) g_cursor[i] = g_offsets[i];
    __syncthreads();

    for (int s = tid; s < NSAMP; s += 1024) {
        int pos = atomicAdd(&g_cursor[(int)g_bk[s]], 1);
        g_order[pos] = s;
    }
}

// ---------------------------------------------------------------------------
// Phase B: one CTA per bucket, 128 threads (thread = r1).
// Stream Bm once per chunk of <=8 samples; accumulate AB in registers;
// reduce against C via smem.
// ---------------------------------------------------------------------------

template <int K>
__device__ __forceinline__ void do_chunk(
    const float* __restrict__ Bm, int t, int cs, float* __restrict__ out,
    const float (&sA)[CHUNK][2][128],
    const float (&sC)[CHUNK][128][2],
    float (&sred)[128][17]) {

    float acc[K][8];
    #pragma unroll
    for (int s = 0; s < K; s++)
        #pragma unroll
        for (int g = 0; g < 8; g++) acc[s][g] = 0.0f;

    #pragma unroll 2
    for (int r0 = 0; r0 < 128; r0++) {
        const float* row = Bm + r0 * 512;
        float v0 = row[t];
        float v1 = row[t + 128];
        float v2 = row[t + 256];
        float v3 = row[t + 384];
        #pragma unroll
        for (int s = 0; s < K; s++) {
            float a0 = sA[s][0][r0];
            float a1 = sA[s][1][r0];
            acc[s][0] = fmaf(a0, v0, acc[s][0]);
            acc[s][1] = fmaf(a0, v1, acc[s][1]);
            acc[s][2] = fmaf(a0, v2, acc[s][2]);
            acc[s][3] = fmaf(a0, v3, acc[s][3]);
            acc[s][4] = fmaf(a1, v0, acc[s][4]);
            acc[s][5] = fmaf(a1, v1, acc[s][5]);
            acc[s][6] = fmaf(a1, v2, acc[s][6]);
            acc[s][7] = fmaf(a1, v3, acc[s][7]);
        }
    }

    // out[g,q2] = sum over r1(=thread) of acc[g] * C[r1,q2]
    #pragma unroll
    for (int s = 0; s < K; s++) {
        float c0 = sC[s][t][0];
        float c1 = sC[s][t][1];
        #pragma unroll
        for (int g = 0; g < 8; g++) {
            sred[t][2 * g]     = acc[s][g] * c0;
            sred[t][2 * g + 1] = acc[s][g] * c1;
        }
        __syncthreads();
        if (t < 16) {
            float sum = 0.0f;
            #pragma unroll
            for (int r = 0; r < 128; r++) sum += sred[r][t];
            out[(size_t)g_order[cs + s] * 16 + t] = sum;
        }
        __syncthreads();
    }
}

__global__ __launch_bounds__(128) void tt_grouped(
    const float* __restrict__ core0,
    const float* __restrict__ core1,
    const float* __restrict__ core2,
    float* __restrict__ out) {

    const int bucket = blockIdx.x;
    const int start = g_offsets[bucket];
    const int end   = g_offsets[bucket + 1];
    if (start >= end) return;

    const int table = bucket / 216;
    const int i1    = bucket - table * 216;
    const float* Bm = core1 + ((size_t)table * 216 + i1) * CORE1_ROW;
    const float* c0t = core0 + (size_t)table * 216 * CORE02_ROW;
    const float* c2t = core2 + (size_t)table * 216 * CORE02_ROW;

    __shared__ float sA[CHUNK][2][128];
    __shared__ float sC[CHUNK][128][2];
    __shared__ float sred[128][17];

    const int t = threadIdx.x;

    for (int cs = start; cs < end; cs += CHUNK) {
        const int k = min(CHUNK, end - cs);

        for (int s = 0; s < k; s++) {
            int sid = g_order[cs + s];
            const float* a = c0t + (size_t)g_i0[sid] * CORE02_ROW;
            sA[s][0][t] = a[t];
            sA[s][1][t] = a[t + 128];
            const float2* c = (const float2*)(c2t + (size_t)g_i2[sid] * CORE02_ROW);
            float2 cc = c[t];
            sC[s][t][0] = cc.x;
            sC[s][t][1] = cc.y;
        }
        __syncthreads();

        switch (k) {
            case 1: do_chunk<1>(Bm, t, cs, out, sA, sC, sred); break;
            case 2: do_chunk<2>(Bm, t, cs, out, sA, sC, sred); break;
            case 3: do_chunk<3>(Bm, t, cs, out, sA, sC, sred); break;
            case 4: do_chunk<4>(Bm, t, cs, out, sA, sC, sred); break;
            case 5: do_chunk<5>(Bm, t, cs, out, sA, sC, sred); break;
            case 6: do_chunk<6>(Bm, t, cs, out, sA, sC, sred); break;
            case 7: do_chunk<7>(Bm, t, cs, out, sA, sC, sred); break;
            default: do_chunk<8>(Bm, t, cs, out, sA, sC, sred); break;
        }
        __syncthreads();
    }
}

// ---------------------------------------------------------------------------
// Launch
// ---------------------------------------------------------------------------
extern "C" void kernel_launch(void* const* d_in, const int* in_sizes, int n_in,
                              void* d_out, int out_size) {
    (void)in_sizes; (void)n_in; (void)out_size;
    const void*  idx   = d_in[0];                 // lS_i [2,1024] int64 (or int32)
    const float* core0 = (const float*)d_in[1];   // [2,216,256]
    const float* core1 = (const float*)d_in[2];   // [2,216,65536]
    const float* core2 = (const float*)d_in[3];   // [2,216,256]
    float* out = (float*)d_out;                   // [2,1024,16]

    build_buckets<<<1, 1024>>>(idx);
    tt_grouped<<<NBUCKET, 128>>>(core0, core1, core2, out);
}

// round 2
// speedup vs baseline: 2.0856x; 2.0856x over previous
#include <cuda_runtime.h>
#include <cstdint>

// ---------------------------------------------------------------------------
// TT embedding lookup, grouped by (table, i1), chunked, r0-sliced.
// P=(216,216,216), Q=(2,4,2), R=(128,128), 2 tables, batch 1024.
// out[t,b,(q0*4+q1)*2+q2] = sum_{r0,r1} A[q0,r0] * Bm[r0, q1*128+r1] * C[r1,q2]
// ---------------------------------------------------------------------------

#define NTAB 2
#define BATCH 1024
#define NSAMP (NTAB * BATCH)
#define P12 46656LL
#define NBUCKET (NTAB * 216)
#define CORE1_ROW 65536   // 128*4*128 floats (256KB)
#define CHUNK 8
#define MAXCHUNKS 688     // 2048/8 + 432 upper bound

__device__ int   g_counts[NBUCKET];
__device__ int   g_offsets[NBUCKET + 1];
__device__ int   g_cursor[NBUCKET];
__device__ int   g_order[NSAMP];
__device__ int   g_i0[NSAMP];
__device__ int   g_i2[NSAMP];
__device__ short g_bk[NSAMP];
__device__ int   g_chunk_bucket[MAXCHUNKS];
__device__ int   g_chunk_start[MAXCHUNKS];
__device__ int   g_nchunks;

// ---------------------------------------------------------------------------
// f32x2 packed-FMA helpers (sm_103a)
// ---------------------------------------------------------------------------
__device__ __forceinline__ unsigned long long pack2(float x, float y) {
    unsigned long long r;
    asm("mov.b64 %0, {%1, %2};" : "=l"(r) : "f"(x), "f"(y));
    return r;
}
__device__ __forceinline__ void unpack2(unsigned long long v, float& x, float& y) {
    asm("mov.b64 {%0, %1}, %2;" : "=f"(x), "=f"(y) : "l"(v));
}
__device__ __forceinline__ void ffma2(unsigned long long& d,
                                      unsigned long long a,
                                      unsigned long long b) {
    asm("fma.rn.f32x2 %0, %1, %2, %0;" : "+l"(d) : "l"(a), "l"(b));
}

// ---------------------------------------------------------------------------
// Phase A: decode indices, bucket-sort by (table,i1), build chunk worklist.
// Single CTA of 1024 threads; prefix sums via Hillis-Steele in smem.
// ---------------------------------------------------------------------------
__global__ void build_buckets(const void* __restrict__ idx_raw) {
    const int tid = threadIdx.x;

    for (int i = tid; i < NBUCKET; i += 1024) g_counts[i] = 0;
    __syncthreads();

    const long long* p64 = (const long long*)idx_raw;
    const int*       p32 = (const int*)idx_raw;
    bool is64 = true;
    #pragma unroll
    for (int j = 0; j < 4; j++) {
        long long v = p64[j];
        if (v < 0 || v >= 10000000LL) is64 = false;
    }

    for (int s = tid; s < NSAMP; s += 1024) {
        long long idx = is64 ? p64[s] : (long long)p32[s];
        int i0 = (int)(idx / P12);
        int i1 = (int)((idx / 216) % 216);
        int i2 = (int)(idx % 216);
        int b = (s >> 10) * 216 + i1;
        g_i0[s] = i0;
        g_i2[s] = i2;
        g_bk[s] = (short)b;
        atomicAdd(&g_counts[b], 1);
    }
    __syncthreads();

    // Parallel inclusive scans over 512 slots (counts and chunk counts).
    __shared__ int scnt[512];
    __shared__ int schk[512];
    int mycnt = 0;
    if (tid < 512) {
        mycnt = (tid < NBUCKET) ? g_counts[tid] : 0;
        scnt[tid] = mycnt;
        schk[tid] = (mycnt + CHUNK - 1) / CHUNK;
    }
    __syncthreads();
    for (int d = 1; d < 512; d <<= 1) {
        int a = 0, b = 0;
        if (tid < 512 && tid >= d) { a = scnt[tid - d]; b = schk[tid - d]; }
        __syncthreads();
        if (tid < 512 && tid >= d) { scnt[tid] += a; schk[tid] += b; }
        __syncthreads();
    }

    if (tid < NBUCKET) {
        int off = scnt[tid] - mycnt;          // exclusive sample offset
        g_offsets[tid] = off;
        g_cursor[tid]  = off;
        int nch    = (mycnt + CHUNK - 1) / CHUNK;
        int chkoff = schk[tid] - nch;         // exclusive chunk offset
        for (int j = 0; j < nch; j++) {
            g_chunk_bucket[chkoff + j] = tid;
            g_chunk_start[chkoff + j]  = off + j * CHUNK;
        }
    }
    if (tid == 0) {
        g_offsets[NBUCKET] = NSAMP;
        g_nchunks = 0;  // set below after scan values visible
    }
    __syncthreads();
    if (tid == 0) g_nchunks = schk[511];
    __syncthreads();

    for (int s = tid; s < NSAMP; s += 1024) {
        int pos = atomicAdd(&g_cursor[(int)g_bk[s]], 1);
        g_order[pos] = s;
    }
}

// ---------------------------------------------------------------------------
// Phase B: one CTA per chunk (<=8 samples sharing the same core1 row).
// 256 threads: slice = t>>7 (r0 half), q1 = (t>>5)&3, r1 quad = 4*(t&31).
// Each thread: one LDG.128 per r0 row, f32x2 FMA into acc[sample][4].
// Epilogue: multiply by C (direct coalesced LDG), warp-shuffle reduce,
// cross-slice combine in smem, single deterministic store per output.
// ---------------------------------------------------------------------------

template <int K>
__device__ __forceinline__ void run_chunk(
    const float* __restrict__ Bm,
    const float* __restrict__ c2t,
    float* __restrict__ out,
    const unsigned long long (&sA)[CHUNK][128],
    const int (&s_sid)[CHUNK], const int (&s_i2)[CHUNK],
    float (&s_red)[8][CHUNK][4]) {

    const int t     = threadIdx.x;
    const int slice = t >> 7;        // 0..1  (r0 rows slice*64 .. +63)
    const int warp  = t >> 5;        // 0..7  == slice*4 + q1
    const int q1    = warp & 3;
    const int m     = t & 31;

    unsigned long long acc[K][4];
    #pragma unroll
    for (int s = 0; s < K; s++)
        #pragma unroll
        for (int j = 0; j < 4; j++) acc[s][j] = 0ULL;

    const float4* base = (const float4*)(Bm + (size_t)(slice * 64) * 512 + q1 * 128 + m * 4);
    // base stride per row = 512 floats = 128 float4s

    #pragma unroll 1
    for (int rb = 0; rb < 64; rb += 4) {
        float4 v0 = __ldg(base + (size_t)(rb + 0) * 128);
        float4 v1 = __ldg(base + (size_t)(rb + 1) * 128);
        float4 v2 = __ldg(base + (size_t)(rb + 2) * 128);
        float4 v3 = __ldg(base + (size_t)(rb + 3) * 128);
        const float4 vv[4] = {v0, v1, v2, v3};
        #pragma unroll
        for (int u = 0; u < 4; u++) {
            const int r = slice * 64 + rb + u;
            unsigned long long b0 = pack2(vv[u].x, vv[u].x);
            unsigned long long b1 = pack2(vv[u].y, vv[u].y);
            unsigned long long b2 = pack2(vv[u].z, vv[u].z);
            unsigned long long b3 = pack2(vv[u].w, vv[u].w);
            #pragma unroll
            for (int s = 0; s < K; s++) {
                unsigned long long a = sA[s][r];
                ffma2(acc[s][0], a, b0);
                ffma2(acc[s][1], a, b1);
                ffma2(acc[s][2], a, b2);
                ffma2(acc[s][3], a, b3);
            }
        }
    }

    // Epilogue: p[q0][q2] = sum_j acc[s][j].{q0} * C[4m+j][q2], reduce over warp.
    #pragma unroll
    for (int s = 0; s < K; s++) {
        const float* c2row = c2t + (size_t)s_i2[s] * 256;
        float4 cA = __ldg((const float4*)(c2row + m * 8));
        float4 cB = __ldg((const float4*)(c2row + m * 8 + 4));
        float p00 = 0.f, p01 = 0.f, p10 = 0.f, p11 = 0.f;
        float f0, f1;
        unpack2(acc[s][0], f0, f1);
        p00 = fmaf(f0, cA.x, p00); p01 = fmaf(f0, cA.y, p01);
        p10 = fmaf(f1, cA.x, p10); p11 = fmaf(f1, cA.y, p11);
        unpack2(acc[s][1], f0, f1);
        p00 = fmaf(f0, cA.z, p00); p01 = fmaf(f0, cA.w, p01);
        p10 = fmaf(f1, cA.z, p10); p11 = fmaf(f1, cA.w, p11);
        unpack2(acc[s][2], f0, f1);
        p00 = fmaf(f0, cB.x, p00); p01 = fmaf(f0, cB.y, p01);
        p10 = fmaf(f1, cB.x, p10); p11 = fmaf(f1, cB.y, p11);
        unpack2(acc[s][3], f0, f1);
        p00 = fmaf(f0, cB.z, p00); p01 = fmaf(f0, cB.w, p01);
        p10 = fmaf(f1, cB.z, p10); p11 = fmaf(f1, cB.w, p11);
        #pragma unroll
        for (int off = 16; off > 0; off >>= 1) {
            p00 += __shfl_xor_sync(0xFFFFFFFFu, p00, off);
            p01 += __shfl_xor_sync(0xFFFFFFFFu, p01, off);
            p10 += __shfl_xor_sync(0xFFFFFFFFu, p10, off);
            p11 += __shfl_xor_sync(0xFFFFFFFFu, p11, off);
        }
        if (m == 0) {
            s_red[warp][s][0] = p00;
            s_red[warp][s][1] = p01;
            s_red[warp][s][2] = p10;
            s_red[warp][s][3] = p11;
        }
    }
    __syncthreads();

    if (t < K * 16) {
        int s = t >> 4, j = t & 15;
        int q0 = j >> 3, q1o = (j >> 1) & 3, q2 = j & 1;
        float sum = s_red[q1o][s][q0 * 2 + q2] + s_red[4 + q1o][s][q0 * 2 + q2];
        out[(size_t)s_sid[s] * 16 + j] = sum;
    }
}

__global__ __launch_bounds__(256, 2) void tt_chunks(
    const float* __restrict__ core0,
    const float* __restrict__ core1,
    const float* __restrict__ core2,
    float* __restrict__ out) {

    const int c = blockIdx.x;
    if (c >= g_nchunks) return;

    const int bucket = g_chunk_bucket[c];
    const int cs     = g_chunk_start[c];
    const int end    = g_offsets[bucket + 1];
    const int k      = min(CHUNK, end - cs);

    const int table = (bucket >= 216) ? 1 : 0;
    const float* Bm  = core1 + (size_t)bucket * CORE1_ROW;
    const float* c0t = core0 + (size_t)table * 216 * 256;
    const float* c2t = core2 + (size_t)table * 216 * 256;

    __shared__ unsigned long long sA[CHUNK][128];  // (a_q0=0, a_q0=1) pairs
    __shared__ int s_sid[CHUNK], s_i2[CHUNK];
    __shared__ float s_red[8][CHUNK][4];

    const int t = threadIdx.x;
    __shared__ int s_i0[CHUNK];
    if (t < k) {
        int sid = g_order[cs + t];
        s_sid[t] = sid;
        s_i0[t]  = g_i0[sid];
        s_i2[t]  = g_i2[sid];
    }
    __syncthreads();

    for (int x = t; x < k * 128; x += 256) {
        int s = x >> 7, r = x & 127;
        const float* a = c0t + (size_t)s_i0[s] * 256;
        sA[s][r] = pack2(a[r], a[r + 128]);
    }
    __syncthreads();

    switch (k) {
        case 1: run_chunk<1>(Bm, c2t, out, sA, s_sid, s_i2, s_red); break;
        case 2: run_chunk<2>(Bm, c2t, out, sA, s_sid, s_i2, s_red); break;
        case 3: run_chunk<3>(Bm, c2t, out, sA, s_sid, s_i2, s_red); break;
        case 4: run_chunk<4>(Bm, c2t, out, sA, s_sid, s_i2, s_red); break;
        case 5: run_chunk<5>(Bm, c2t, out, sA, s_sid, s_i2, s_red); break;
        case 6: run_chunk<6>(Bm, c2t, out, sA, s_sid, s_i2, s_red); break;
        case 7: run_chunk<7>(Bm, c2t, out, sA, s_sid, s_i2, s_red); break;
        default: run_chunk<8>(Bm, c2t, out, sA, s_sid, s_i2, s_red); break;
    }
}

// ---------------------------------------------------------------------------
// Launch
// ---------------------------------------------------------------------------
extern "C" void kernel_launch(void* const* d_in, const int* in_sizes, int n_in,
                              void* d_out, int out_size) {
    (void)in_sizes; (void)n_in; (void)out_size;
    const void*  idx   = d_in[0];                 // lS_i [2,1024] int64 (or int32)
    const float* core0 = (const float*)d_in[1];   // [2,216,256]
    const float* core1 = (const float*)d_in[2];   // [2,216,65536]
    const float* core2 = (const float*)d_in[3];   // [2,216,256]
    float* out = (float*)d_out;                   // [2,1024,16]

    build_buckets<<<1, 1024>>>(idx);
    tt_chunks<<<MAXCHUNKS, 256>>>(core0, core1, core2, out);
}

// round 3
// speedup vs baseline: 2.0886x; 1.0014x over previous
#include <cuda_runtime.h>
#include <cstdint>

// ---------------------------------------------------------------------------
// TT embedding lookup: grouped by (table,i1), chunked (<=8 samples), each
// chunk split over 2 CTAs (r0 halves). core1 slab streamed via cp.async.bulk
// into a 4-stage smem ring; compute = f32x2 FFMA from smem.
// P=(216,216,216), Q=(2,4,2), R=(128,128), 2 tables, batch 1024.
// ---------------------------------------------------------------------------

#define NTAB 2
#define BATCH 1024
#define NSAMP (NTAB * BATCH)
#define P12 46656LL
#define NBUCKET (NTAB * 216)
#define CORE1_ROW 65536     // floats per core1 slab (256 KB)
#define CHUNK 8
#define MAXCHUNKS 688

// dynamic smem layout (bytes)
#define SM_BUF    0          // 4 stages x 16384
#define SM_ADUP   65536      // 64 rows x 2 q0 x 8 samples x u64 = 8192
#define SM_RED    73728      // 8 warps x 8 samples x 4 floats = 1024
#define SM_SID    74752      // 8 ints
#define SM_I2     74784
#define SM_I0     74816
#define SM_MBAR   74848      // 4 mbarriers x 8B
#define SM_TOTAL  74880
#define STAGE_BYTES 16384

__device__ int g_offsets[NBUCKET + 1];
__device__ int g_order[NSAMP];
__device__ int g_i0[NSAMP];
__device__ int g_i2[NSAMP];
__device__ int g_chunk_bucket[MAXCHUNKS];
__device__ int g_chunk_start[MAXCHUNKS];
__device__ int g_nchunks;

// ---------------------------------------------------------------------------
// helpers
// ---------------------------------------------------------------------------
__device__ __forceinline__ unsigned long long pack2(float x, float y) {
    unsigned long long r;
    asm("mov.b64 %0, {%1, %2};" : "=l"(r) : "f"(x), "f"(y));
    return r;
}
__device__ __forceinline__ void unpack2(unsigned long long v, float& x, float& y) {
    asm("mov.b64 {%0, %1}, %2;" : "=f"(x), "=f"(y) : "l"(v));
}
__device__ __forceinline__ void ffma2(unsigned long long& d,
                                      unsigned long long a,
                                      unsigned long long b) {
    asm("fma.rn.f32x2 %0, %1, %2, %0;" : "+l"(d) : "l"(a), "l"(b));
}
__device__ __forceinline__ void mbar_init(uint32_t a, uint32_t cnt) {
    asm volatile("mbarrier.init.shared.b64 [%0], %1;" :: "r"(a), "r"(cnt) : "memory");
}
__device__ __forceinline__ void mbar_expect(uint32_t a, uint32_t bytes) {
    asm volatile("mbarrier.arrive.expect_tx.shared.b64 _, [%0], %1;"
                 :: "r"(a), "r"(bytes) : "memory");
}
__device__ __forceinline__ void mbar_wait(uint32_t a, uint32_t ph) {
    uint32_t done;
    asm volatile(
        "{\n\t.reg .pred p;\n\t"
        "mbarrier.try_wait.parity.acquire.cta.shared::cta.b64 p, [%1], %2;\n\t"
        "selp.b32 %0, 1, 0, p;\n\t}"
        : "=r"(done) : "r"(a), "r"(ph) : "memory");
    if (!done) {
        asm volatile(
            "{\n\t.reg .pred P1;\n"
            "W%=:\n\t"
            "mbarrier.try_wait.parity.acquire.cta.shared::cta.b64 P1, [%0], %1, 0x989680;\n\t"
            "@P1 bra.uni D%=;\n\t"
            "bra.uni W%=;\n"
            "D%=:\n\t}"
            :: "r"(a), "r"(ph) : "memory");
    }
}
__device__ __forceinline__ void bulk_copy(uint32_t dst, const void* src,
                                          uint32_t bytes, uint32_t mbar) {
    asm volatile(
        "cp.async.bulk.shared::cta.global.mbarrier::complete_tx::bytes [%0], [%1], %2, [%3];"
        :: "r"(dst), "l"(src), "r"(bytes), "r"(mbar) : "memory");
}

// ---------------------------------------------------------------------------
// Phase A: decode, bucket-sort (smem atomics), build chunk list, zero output.
// ---------------------------------------------------------------------------
__global__ void build_buckets(const void* __restrict__ idx_raw,
                              float* __restrict__ out) {
    const int tid = threadIdx.x;  // 1024
    __shared__ int   scnt[512];
    __shared__ int   schk[512];
    __shared__ int   scur[NBUCKET];
    __shared__ short sbk[NSAMP];

    // zero the output (atomic accumulation target)
    #pragma unroll
    for (int i = tid; i < NSAMP * 16; i += 1024) out[i] = 0.0f;

    if (tid < 512) scnt[tid] = 0;
    __syncthreads();

    const long long* p64 = (const long long*)idx_raw;
    const int*       p32 = (const int*)idx_raw;
    bool is64 = true;
    #pragma unroll
    for (int j = 0; j < 4; j++) {
        long long v = p64[j];
        if (v < 0 || v >= 10000000LL) is64 = false;
    }

    for (int s = tid; s < NSAMP; s += 1024) {
        long long idx = is64 ? p64[s] : (long long)p32[s];
        int i0 = (int)(idx / P12);
        int i1 = (int)((idx / 216) % 216);
        int i2 = (int)(idx % 216);
        int b = (s >> 10) * 216 + i1;
        g_i0[s] = i0;
        g_i2[s] = i2;
        sbk[s] = (short)b;
        atomicAdd(&scnt[b], 1);
    }
    __syncthreads();

    int mycnt = 0;
    if (tid < 512) {
        mycnt = scnt[tid];
        schk[tid] = (mycnt + CHUNK - 1) / CHUNK;
    }
    __syncthreads();
    for (int d = 1; d < 512; d <<= 1) {
        int a = 0, b = 0;
        if (tid < 512 && tid >= d) { a = scnt[tid - d]; b = schk[tid - d]; }
        __syncthreads();
        if (tid < 512 && tid >= d) { scnt[tid] += a; schk[tid] += b; }
        __syncthreads();
    }

    if (tid < NBUCKET) {
        int off = scnt[tid] - mycnt;
        g_offsets[tid] = off;
        scur[tid] = off;
        int nch = (mycnt + CHUNK - 1) / CHUNK;
        int chkoff = schk[tid] - nch;
        for (int j = 0; j < nch; j++) {
            g_chunk_bucket[chkoff + j] = tid;
            g_chunk_start[chkoff + j]  = off + j * CHUNK;
        }
    }
    if (tid == 0) {
        g_offsets[NBUCKET] = NSAMP;
        g_nchunks = 0;
    }
    __syncthreads();
    if (tid == 0) g_nchunks = schk[511];
    __syncthreads();

    for (int s = tid; s < NSAMP; s += 1024) {
        int pos = atomicAdd(&scur[(int)sbk[s]], 1);
        g_order[pos] = s;
    }
}

// ---------------------------------------------------------------------------
// Phase B compute body, templated on chunk size K.
// Thread map: rp = t>>7 (row parity), u = t&127 (float4 column), m = u&31.
// acc[s][q0][cp]: u64 = 2 adjacent columns of AB for (sample, q0).
// ---------------------------------------------------------------------------
template <int K>
__device__ __forceinline__ void run_chunk(
    char* smem, uint32_t smem_u32,
    const float* __restrict__ Bm_h,
    const float* __restrict__ c2t,
    float* __restrict__ out) {

    const int t    = threadIdx.x;
    const int rp   = t >> 7;
    const int u    = t & 127;
    const int m    = u & 31;
    const int warp = t >> 5;

    unsigned long long acc[K][2][2];
    #pragma unroll
    for (int s = 0; s < K; s++)
        #pragma unroll
        for (int q0 = 0; q0 < 2; q0++) { acc[s][q0][0] = 0ULL; acc[s][q0][1] = 0ULL; }

    #pragma unroll 1
    for (int it = 0; it < 8; it++) {
        const int buf = it & 3;
        mbar_wait(smem_u32 + SM_MBAR + buf * 8, (it >> 2) & 1);

        #pragma unroll
        for (int rr = 0; rr < 4; rr++) {
            const int rl = rp + rr * 2;
            ulonglong2 bv = *(const ulonglong2*)(smem + SM_BUF + buf * STAGE_BYTES
                                                 + rl * 2048 + u * 16);
            const int Lr = it * 8 + rl;
            const ulonglong2* ar = (const ulonglong2*)(smem + SM_ADUP + Lr * 128);
            #pragma unroll
            for (int q0 = 0; q0 < 2; q0++) {
                #pragma unroll
                for (int s2 = 0; s2 < (K + 1) / 2; s2++) {
                    ulonglong2 ap = ar[q0 * 4 + s2];
                    ffma2(acc[2 * s2][q0][0], bv.x, ap.x);
                    ffma2(acc[2 * s2][q0][1], bv.y, ap.x);
                    if (2 * s2 + 1 < K) {
                        ffma2(acc[2 * s2 + 1][q0][0], bv.x, ap.y);
                        ffma2(acc[2 * s2 + 1][q0][1], bv.y, ap.y);
                    }
                }
            }
        }
        __syncthreads();
        if (t == 0 && it < 4) {
            uint32_t mb = smem_u32 + SM_MBAR + buf * 8;
            mbar_expect(mb, STAGE_BYTES);
            bulk_copy(smem_u32 + SM_BUF + buf * STAGE_BYTES,
                      (const char*)Bm_h + (size_t)(it + 4) * STAGE_BYTES,
                      STAGE_BYTES, mb);
        }
    }

    // Epilogue: contract with C, warp reduce, combine parities, atomicAdd.
    float* s_red = (float*)(smem + SM_RED);          // [8 warps][8][4]
    const int* s_sid = (const int*)(smem + SM_SID);
    const int* s_i2  = (const int*)(smem + SM_I2);

    #pragma unroll
    for (int s = 0; s < K; s++) {
        const float* c2row = c2t + (size_t)s_i2[s] * 256;
        float4 cA = __ldg((const float4*)(c2row + m * 8));
        float4 cB = __ldg((const float4*)(c2row + m * 8 + 4));
        float x0, x1, x2, x3, y0, y1, y2, y3;
        unpack2(acc[s][0][0], x0, x1);
        unpack2(acc[s][0][1], x2, x3);
        unpack2(acc[s][1][0], y0, y1);
        unpack2(acc[s][1][1], y2, y3);
        float p00 = fmaf(x0, cA.x, fmaf(x1, cA.z, fmaf(x2, cB.x, x3 * cB.z)));
        float p01 = fmaf(x0, cA.y, fmaf(x1, cA.w, fmaf(x2, cB.y, x3 * cB.w)));
        float p10 = fmaf(y0, cA.x, fmaf(y1, cA.z, fmaf(y2, cB.x, y3 * cB.z)));
        float p11 = fmaf(y0, cA.y, fmaf(y1, cA.w, fmaf(y2, cB.y, y3 * cB.w)));
        #pragma unroll
        for (int off = 16; off > 0; off >>= 1) {
            p00 += __shfl_xor_sync(0xFFFFFFFFu, p00, off);
            p01 += __shfl_xor_sync(0xFFFFFFFFu, p01, off);
            p10 += __shfl_xor_sync(0xFFFFFFFFu, p10, off);
            p11 += __shfl_xor_sync(0xFFFFFFFFu, p11, off);
        }
        if (m == 0) {
            float* r = s_red + (warp * 8 + s) * 4;
            r[0] = p00; r[1] = p01; r[2] = p10; r[3] = p11;
        }
    }
    __syncthreads();

    if (t < K * 16) {
        int s = t >> 4, j = t & 15;
        int q0 = j >> 3, q1 = (j >> 1) & 3, q2 = j & 1;
        float v = s_red[(q1 * 8 + s) * 4 + q0 * 2 + q2]
                + s_red[((4 + q1) * 8 + s) * 4 + q0 * 2 + q2];
        atomicAdd(&out[(size_t)s_sid[s] * 16 + j], v);
    }
}

__global__ __launch_bounds__(256, 2) void tt_chunks(
    const float* __restrict__ core0,
    const float* __restrict__ core1,
    const float* __restrict__ core2,
    float* __restrict__ out) {

    extern __shared__ char smem[];
    const int bx = blockIdx.x;
    const int c = bx >> 1;
    const int h = bx & 1;
    if (c >= g_nchunks) return;

    const int bucket = g_chunk_bucket[c];
    const int cs     = g_chunk_start[c];
    const int end    = g_offsets[bucket + 1];
    const int k      = min(CHUNK, end - cs);
    const int table  = (bucket >= 216) ? 1 : 0;

    const float* Bm_h = core1 + (size_t)bucket * CORE1_ROW + (size_t)h * 64 * 512;
    const float* c0t  = core0 + (size_t)table * 216 * 256;
    const float* c2t  = core2 + (size_t)table * 216 * 256;

    const uint32_t smem_u32 = (uint32_t)__cvta_generic_to_shared(smem);
    const int t = threadIdx.x;

    int* s_sid = (int*)(smem + SM_SID);
    int* s_i0  = (int*)(smem + SM_I0);
    int* s_i2  = (int*)(smem + SM_I2);
    if (t < k) {
        int sid = g_order[cs + t];
        s_sid[t] = sid;
        s_i0[t]  = g_i0[sid];
        s_i2[t]  = g_i2[sid];
    }
    if (t == 0) {
        #pragma unroll
        for (int j = 0; j < 4; j++) mbar_init(smem_u32 + SM_MBAR + j * 8, 1);
        asm volatile("fence.proxy.async.shared::cta;" ::: "memory");
    }
    __syncthreads();

    if (t == 0) {
        #pragma unroll
        for (int j = 0; j < 4; j++) {
            uint32_t mb = smem_u32 + SM_MBAR + j * 8;
            mbar_expect(mb, STAGE_BYTES);
            bulk_copy(smem_u32 + SM_BUF + j * STAGE_BYTES,
                      (const char*)Bm_h + (size_t)j * STAGE_BYTES, STAGE_BYTES, mb);
        }
    }

    // Stage duplicated A broadcast pairs: sAdup[Lr][q0][s] = (a,a).
    unsigned long long* adup = (unsigned long long*)(smem + SM_ADUP);
    for (int x = t; x < k * 128; x += 256) {
        int s = x >> 7, y = x & 127, q0 = y >> 6, Lr = y & 63;
        const float* a = c0t + (size_t)s_i0[s] * 256;
        float av = __ldg(a + q0 * 128 + h * 64 + Lr);
        adup[(Lr * 2 + q0) * 8 + s] = pack2(av, av);
    }
    __syncthreads();

    switch (k) {
        case 1: run_chunk<1>(smem, smem_u32, Bm_h, c2t, out); break;
        case 2: run_chunk<2>(smem, smem_u32, Bm_h, c2t, out); break;
        case 3: run_chunk<3>(smem, smem_u32, Bm_h, c2t, out); break;
        case 4: run_chunk<4>(smem, smem_u32, Bm_h, c2t, out); break;
        case 5: run_chunk<5>(smem, smem_u32, Bm_h, c2t, out); break;
        case 6: run_chunk<6>(smem, smem_u32, Bm_h, c2t, out); break;
        case 7: run_chunk<7>(smem, smem_u32, Bm_h, c2t, out); break;
        default: run_chunk<8>(smem, smem_u32, Bm_h, c2t, out); break;
    }
}

// ---------------------------------------------------------------------------
// Launch
// ---------------------------------------------------------------------------
extern "C" void kernel_launch(void* const* d_in, const int* in_sizes, int n_in,
                              void* d_out, int out_size) {
    (void)in_sizes; (void)n_in; (void)out_size;
    const void*  idx   = d_in[0];                 // lS_i [2,1024] int64 (or int32)
    const float* core0 = (const float*)d_in[1];   // [2,216,256]
    const float* core1 = (const float*)d_in[2];   // [2,216,65536]
    const float* core2 = (const float*)d_in[3];   // [2,216,256]
    float* out = (float*)d_out;                   // [2,1024,16]

    cudaFuncSetAttribute(tt_chunks, cudaFuncAttributeMaxDynamicSharedMemorySize,
                         SM_TOTAL);

    build_buckets<<<1, 1024>>>(idx, out);
    tt_chunks<<<2 * MAXCHUNKS, 256, SM_TOTAL>>>(core0, core1, core2, out);
}

// round 5
// speedup vs baseline: 2.1527x; 1.0307x over previous
#include <cuda_runtime.h>
#include <cstdint>

// ---------------------------------------------------------------------------
// TT embedding lookup: grouped by (table,i1), chunks of <=8 samples, each
// chunk split over 4 CTAs (32-row quarters of the 256KB core1 slab, 64KB each).
// core1 streamed via cp.async.bulk through a 3-stage smem ring with per-stage
// __syncthreads refill (single refill per CTA). f32x2 FFMA, sample-pair packed
// accumulators (16 u64 = 32 regs) -> 4 CTAs x 256 threads per SM.
// ---------------------------------------------------------------------------

#define NTAB 2
#define BATCH 1024
#define NSAMP (NTAB * BATCH)
#define P12 46656LL
#define NBUCKET (NTAB * 216)
#define CORE1_ROW 65536
#define CHUNK 8
#define MAXCHUNKS 688
#define STAGE_BYTES 16384

// dynamic smem layout (bytes)
#define SM_BUF    0          // 3 x 16384 = 49152
#define SM_APK    49152      // 32 rows x 2 q0 x 4 u64 (sample pairs) = 2048
#define SM_RED    51200      // 8 warps x 8 samples x 4 floats = 1024
#define SM_SID    52224      // 8 ints
#define SM_I2     52256
#define SM_I0     52288
#define SM_FULL   52320      // 3 mbarriers x 8B
#define SM_TOTAL  52352

__device__ int g_offsets[NBUCKET + 1];
__device__ int g_order[NSAMP];
__device__ int g_i0[NSAMP];
__device__ int g_i2[NSAMP];
__device__ int g_chunk_bucket[MAXCHUNKS];
__device__ int g_chunk_start[MAXCHUNKS];
__device__ int g_nchunks;

// ---------------------------------------------------------------------------
// helpers
// ---------------------------------------------------------------------------
__device__ __forceinline__ unsigned long long pack2(float x, float y) {
    unsigned long long r;
    asm("mov.b64 %0, {%1, %2};" : "=l"(r) : "f"(x), "f"(y));
    return r;
}
__device__ __forceinline__ void unpack2(unsigned long long v, float& x, float& y) {
    asm("mov.b64 {%0, %1}, %2;" : "=f"(x), "=f"(y) : "l"(v));
}
__device__ __forceinline__ void ffma2(unsigned long long& d,
                                      unsigned long long a,
                                      unsigned long long b) {
    asm("fma.rn.f32x2 %0, %1, %2, %0;" : "+l"(d) : "l"(a), "l"(b));
}
__device__ __forceinline__ void mbar_init(uint32_t a, uint32_t cnt) {
    asm volatile("mbarrier.init.shared.b64 [%0], %1;" :: "r"(a), "r"(cnt) : "memory");
}
__device__ __forceinline__ void mbar_expect(uint32_t a, uint32_t bytes) {
    asm volatile("mbarrier.arrive.expect_tx.shared.b64 _, [%0], %1;"
                 :: "r"(a), "r"(bytes) : "memory");
}
__device__ __forceinline__ void mbar_wait(uint32_t a, uint32_t ph) {
    uint32_t done;
    asm volatile(
        "{\n\t.reg .pred p;\n\t"
        "mbarrier.try_wait.parity.acquire.cta.shared::cta.b64 p, [%1], %2;\n\t"
        "selp.b32 %0, 1, 0, p;\n\t}"
        : "=r"(done) : "r"(a), "r"(ph) : "memory");
    if (!done) {
        asm volatile(
            "{\n\t.reg .pred P1;\n"
            "W%=:\n\t"
            "mbarrier.try_wait.parity.acquire.cta.shared::cta.b64 P1, [%0], %1, 0x989680;\n\t"
            "@P1 bra.uni D%=;\n\t"
            "bra.uni W%=;\n"
            "D%=:\n\t}"
            :: "r"(a), "r"(ph) : "memory");
    }
}
__device__ __forceinline__ void bulk_copy(uint32_t dst, const void* src,
                                          uint32_t bytes, uint32_t mbar) {
    asm volatile(
        "cp.async.bulk.shared::cta.global.mbarrier::complete_tx::bytes [%0], [%1], %2, [%3];"
        :: "r"(dst), "l"(src), "r"(bytes), "r"(mbar) : "memory");
}

// ---------------------------------------------------------------------------
// Phase A: decode, bucket-sort (smem atomics), build chunk list, zero output.
// ---------------------------------------------------------------------------
__global__ void build_buckets(const void* __restrict__ idx_raw,
                              float* __restrict__ out) {
    const int tid = threadIdx.x;  // 1024
    __shared__ int   scnt[512];
    __shared__ int   schk[512];
    __shared__ int   scur[NBUCKET];
    __shared__ short sbk[NSAMP];

    float4* o4 = (float4*)out;
    #pragma unroll
    for (int i = tid; i < NSAMP * 4; i += 1024)
        o4[i] = make_float4(0.f, 0.f, 0.f, 0.f);

    if (tid < 512) scnt[tid] = 0;
    __syncthreads();

    const long long* p64 = (const long long*)idx_raw;
    const int*       p32 = (const int*)idx_raw;
    bool is64 = true;
    #pragma unroll
    for (int j = 0; j < 4; j++) {
        long long v = p64[j];
        if (v < 0 || v >= 10000000LL) is64 = false;
    }

    for (int s = tid; s < NSAMP; s += 1024) {
        long long idx = is64 ? p64[s] : (long long)p32[s];
        int i0 = (int)(idx / P12);
        int i1 = (int)((idx / 216) % 216);
        int i2 = (int)(idx % 216);
        int b = (s >> 10) * 216 + i1;
        g_i0[s] = i0;
        g_i2[s] = i2;
        sbk[s] = (short)b;
        atomicAdd(&scnt[b], 1);
    }
    __syncthreads();

    int mycnt = 0;
    if (tid < 512) {
        mycnt = scnt[tid];
        schk[tid] = (mycnt + CHUNK - 1) / CHUNK;
    }
    __syncthreads();
    for (int d = 1; d < 512; d <<= 1) {
        int a = 0, b = 0;
        if (tid < 512 && tid >= d) { a = scnt[tid - d]; b = schk[tid - d]; }
        __syncthreads();
        if (tid < 512 && tid >= d) { scnt[tid] += a; schk[tid] += b; }
        __syncthreads();
    }

    if (tid < NBUCKET) {
        int off = scnt[tid] - mycnt;
        g_offsets[tid] = off;
        scur[tid] = off;
        int nch = (mycnt + CHUNK - 1) / CHUNK;
        int chkoff = schk[tid] - nch;
        for (int j = 0; j < nch; j++) {
            g_chunk_bucket[chkoff + j] = tid;
            g_chunk_start[chkoff + j]  = off + j * CHUNK;
        }
    }
    if (tid == 0) g_offsets[NBUCKET] = NSAMP;
    __syncthreads();
    if (tid == 0) g_nchunks = schk[511];
    __syncthreads();

    for (int s = tid; s < NSAMP; s += 1024) {
        int pos = atomicAdd(&scur[(int)sbk[s]], 1);
        g_order[pos] = s;
    }
}

// ---------------------------------------------------------------------------
// Phase B compute body. K2 = number of sample-pairs (ceil(k/2)).
// Thread u=t covers columns (2u, 2u+1) of the 512-wide row.
// acc[spair][q0][col] f32x2: lanes = (sample 2*spair, sample 2*spair+1).
// 4 stages of 8 rows each (32 rows total per quarter-slab), ring of 3 bufs.
// ---------------------------------------------------------------------------
template <int K2>
__device__ __forceinline__ void run_chunk(
    char* smem, uint32_t smem_u32, int k,
    const float* __restrict__ Bm_q,
    const float* __restrict__ c2t,
    float* __restrict__ out) {

    const int t    = threadIdx.x;   // 0..255
    const int lane = t & 31;
    const int warp = t >> 5;        // 0..7

    unsigned long long acc[K2][2][2];
    #pragma unroll
    for (int sp = 0; sp < K2; sp++)
        #pragma unroll
        for (int q0 = 0; q0 < 2; q0++) { acc[sp][q0][0] = 0ULL; acc[sp][q0][1] = 0ULL; }

    const uint32_t mb_full = smem_u32 + SM_FULL;

    #pragma unroll 1
    for (int it = 0; it < 4; it++) {
        const int buf = (it < 3) ? it : 0;
        mbar_wait(mb_full + buf * 8, (it < 3) ? 0u : 1u);

        #pragma unroll
        for (int rr = 0; rr < 8; rr++) {
            float2 b = *(const float2*)(smem + SM_BUF + buf * STAGE_BYTES
                                        + rr * 2048 + t * 8);
            unsigned long long b0 = pack2(b.x, b.x);
            unsigned long long b1 = pack2(b.y, b.y);
            const int Lr = it * 8 + rr;
            const ulonglong2* ar = (const ulonglong2*)(smem + SM_APK + Lr * 64);
            #pragma unroll
            for (int q0 = 0; q0 < 2; q0++) {
                ulonglong2 aa = ar[q0 * 2];
                ffma2(acc[0][q0][0], b0, aa.x);
                ffma2(acc[0][q0][1], b1, aa.x);
                if (K2 > 1) { ffma2(acc[1][q0][0], b0, aa.y);
                              ffma2(acc[1][q0][1], b1, aa.y); }
                if (K2 > 2) {
                    ulonglong2 ab = ar[q0 * 2 + 1];
                    ffma2(acc[2][q0][0], b0, ab.x);
                    ffma2(acc[2][q0][1], b1, ab.x);
                    if (K2 > 3) { ffma2(acc[3][q0][0], b0, ab.y);
                                  ffma2(acc[3][q0][1], b1, ab.y); }
                }
            }
        }
        __syncthreads();
        if (t == 0 && it == 0) {
            // refill buf 0 with stage 3 (rows 24..31)
            mbar_expect(mb_full, STAGE_BYTES);
            bulk_copy(smem_u32 + SM_BUF,
                      (const char*)Bm_q + (size_t)3 * STAGE_BYTES,
                      STAGE_BYTES, mb_full);
        }
    }

    // Epilogue: contract with C, warp reduce over r1, combine in smem.
    float* s_red = (float*)(smem + SM_RED);           // [8 warps][8][4]
    const int* s_sid = (const int*)(smem + SM_SID);
    const int* s_i2  = (const int*)(smem + SM_I2);
    const int r1p = t & 63;   // r1 pair index: columns r1=2*r1p, 2*r1p+1

    #pragma unroll
    for (int sp = 0; sp < K2; sp++) {
        float x00, x01, x10, x11;   // sample 2*sp:   [q0][col]
        float y00, y01, y10, y11;   // sample 2*sp+1
        unpack2(acc[sp][0][0], x00, y00);
        unpack2(acc[sp][0][1], x01, y01);
        unpack2(acc[sp][1][0], x10, y10);
        unpack2(acc[sp][1][1], x11, y11);
        #pragma unroll
        for (int h2 = 0; h2 < 2; h2++) {
            int s = 2 * sp + h2;
            const float* c2row = c2t + (size_t)s_i2[s] * 256;
            float4 cv = __ldg((const float4*)(c2row + r1p * 4));
            float A0 = h2 ? y00 : x00, A1 = h2 ? y01 : x01;
            float B0 = h2 ? y10 : x10, B1 = h2 ? y11 : x11;
            float p00 = fmaf(A0, cv.x, A1 * cv.z);
            float p01 = fmaf(A0, cv.y, A1 * cv.w);
            float p10 = fmaf(B0, cv.x, B1 * cv.z);
            float p11 = fmaf(B0, cv.y, B1 * cv.w);
            #pragma unroll
            for (int off = 16; off > 0; off >>= 1) {
                p00 += __shfl_xor_sync(0xFFFFFFFFu, p00, off);
                p01 += __shfl_xor_sync(0xFFFFFFFFu, p01, off);
                p10 += __shfl_xor_sync(0xFFFFFFFFu, p10, off);
                p11 += __shfl_xor_sync(0xFFFFFFFFu, p11, off);
            }
            if (lane == 0) {
                float* r = s_red + (warp * 8 + s) * 4;
                r[0] = p00; r[1] = p01; r[2] = p10; r[3] = p11;
            }
        }
    }
    __syncthreads();

    if (t < k * 16) {
        int s = t >> 4, j = t & 15;
        int q0 = j >> 3, q1 = (j >> 1) & 3, q2 = j & 1;
        int idx = q0 * 2 + q2;
        int w0 = 2 * q1;
        float v = s_red[((w0)     * 8 + s) * 4 + idx]
                + s_red[((w0 + 1) * 8 + s) * 4 + idx];
        atomicAdd(&out[(size_t)s_sid[s] * 16 + j], v);
    }
}

__global__ __launch_bounds__(256, 4) void tt_chunks(
    const float* __restrict__ core0,
    const float* __restrict__ core1,
    const float* __restrict__ core2,
    float* __restrict__ out) {

    extern __shared__ char smem[];
    const int bx = blockIdx.x;
    const int c = bx >> 2;
    const int h = bx & 3;          // quarter: rows 32h..32h+31
    if (c >= g_nchunks) return;

    const int bucket = g_chunk_bucket[c];
    const int cs     = g_chunk_start[c];
    const int end    = g_offsets[bucket + 1];
    const int k      = min(CHUNK, end - cs);
    const int table  = (bucket >= 216) ? 1 : 0;

    const float* Bm_q = core1 + (size_t)bucket * CORE1_ROW + (size_t)h * 32 * 512;
    const float* c0t  = core0 + (size_t)table * 216 * 256;
    const float* c2t  = core2 + (size_t)table * 216 * 256;

    const uint32_t smem_u32 = (uint32_t)__cvta_generic_to_shared(smem);
    const int t = threadIdx.x;

    int* s_sid = (int*)(smem + SM_SID);
    int* s_i0  = (int*)(smem + SM_I0);
    int* s_i2  = (int*)(smem + SM_I2);
    if (t < CHUNK) {
        if (t < k) {
            int sid = g_order[cs + t];
            s_sid[t] = sid;
            s_i0[t]  = g_i0[sid];
            s_i2[t]  = g_i2[sid];
        } else {
            s_i2[t] = 0;   // safe epilogue loads for padded samples
        }
    }
    // zero A-pack (padded samples must contribute 0): 256 u64
    unsigned long long* apk = (unsigned long long*)(smem + SM_APK);
    apk[t] = 0ULL;
    if (t == 0) {
        #pragma unroll
        for (int j = 0; j < 3; j++) mbar_init(smem_u32 + SM_FULL + j * 8, 1);
        asm volatile("fence.proxy.async.shared::cta;" ::: "memory");
    }
    __syncthreads();

    if (t == 0) {
        #pragma unroll
        for (int j = 0; j < 3; j++) {
            uint32_t mb = smem_u32 + SM_FULL + j * 8;
            mbar_expect(mb, STAGE_BYTES);
            bulk_copy(smem_u32 + SM_BUF + j * STAGE_BYTES,
                      (const char*)Bm_q + (size_t)j * STAGE_BYTES, STAGE_BYTES, mb);
        }
    }

    // Stage A sample-pair packs: apk[(Lr*2+q0)*4 + s/2] lanes = (s even, s odd)
    float* apkf = (float*)apk;
    for (int x = t; x < k * 64; x += 256) {
        int s = x >> 6, y = x & 63, q0 = y >> 5, Lr = y & 31;
        float av = __ldg(c0t + (size_t)s_i0[s] * 256 + q0 * 128 + h * 32 + Lr);
        apkf[(((Lr * 2 + q0) * 4) + (s >> 1)) * 2 + (s & 1)] = av;
    }
    __syncthreads();

    switch ((k + 1) >> 1) {
        case 1: run_chunk<1>(smem, smem_u32, k, Bm_q, c2t, out); break;
        case 2: run_chunk<2>(smem, smem_u32, k, Bm_q, c2t, out); break;
        case 3: run_chunk<3>(smem, smem_u32, k, Bm_q, c2t, out); break;
        default: run_chunk<4>(smem, smem_u32, k, Bm_q, c2t, out); break;
    }
}

// ---------------------------------------------------------------------------
// Launch
// ---------------------------------------------------------------------------
extern "C" void kernel_launch(void* const* d_in, const int* in_sizes, int n_in,
                              void* d_out, int out_size) {
    (void)in_sizes; (void)n_in; (void)out_size;
    const void*  idx   = d_in[0];                 // lS_i [2,1024] int64 (or int32)
    const float* core0 = (const float*)d_in[1];   // [2,216,256]
    const float* core1 = (const float*)d_in[2];   // [2,216,65536]
    const float* core2 = (const float*)d_in[3];   // [2,216,256]
    float* out = (float*)d_out;                   // [2,1024,16]

    cudaFuncSetAttribute(tt_chunks, cudaFuncAttributeMaxDynamicSharedMemorySize,
                         SM_TOTAL);

    build_buckets<<<1, 1024>>>(idx, out);
    tt_chunks<<<4 * MAXCHUNKS, 256, SM_TOTAL>>>(core0, core1, core2, out);
}